// round 7
// baseline (speedup 1.0000x reference)
#include <cuda_runtime.h>

#define B_   32
#define T_   512
#define NS_  32
#define H_   128
#define G_   512      // 4*H
#define KT_  160      // H + NS (h part then x part)
#define KS_  96       // smem-resident k rows
#define KR_  64       // register-resident k rows

// Transposed combined weights: Wt[n][k][r]; k<128 -> W_hh[n][r][k], else W_ih[n][r][k-128]
__device__ float g_Wt[(size_t)NS_ * KT_ * G_];

static __device__ __forceinline__ unsigned long long pk2(float x) {
    unsigned long long r;
    asm("mov.b64 %0, {%1, %1};" : "=l"(r) : "f"(x));
    return r;
}
static __device__ __forceinline__ void upk2(unsigned long long v, float& a, float& b) {
    asm("mov.b64 {%0, %1}, %2;" : "=f"(a), "=f"(b) : "l"(v));
}
static __device__ __forceinline__ unsigned long long ff2(unsigned long long a,
                                                         unsigned long long b,
                                                         unsigned long long c) {
    unsigned long long d;
    asm("fma.rn.f32x2 %0, %1, %2, %3;" : "=l"(d) : "l"(a), "l"(b), "l"(c));
    return d;
}
static __device__ __forceinline__ float sigm_(float x) {
    float e = __expf(-x);
    float r;
    asm("rcp.approx.f32 %0, %1;" : "=f"(r) : "f"(1.0f + e));
    return r;
}
static __device__ __forceinline__ float tanh_(float x) {
    return fmaf(2.0f, sigm_(2.0f * x), -1.0f);
}

// ---------------- prep: transpose weights into g_Wt (coalesced writes) ----
__global__ void prep_k(const float* __restrict__ Whh, const float* __restrict__ Wih) {
    const int k = blockIdx.x;        // 0..159
    const int n = blockIdx.y;        // 0..31
    const int r = threadIdx.x;       // 0..511
    float v;
    if (k < H_) v = Whh[((size_t)n * G_ + r) * H_ + k];
    else        v = Wih[((size_t)n * G_ + r) * NS_ + (k - H_)];
    g_Wt[((size_t)n * KT_ + k) * G_ + r] = v;
}

// ---------------- persistent LSTM kernel ----------------
// smem floats: sWs[96][512] | sv[160][8] | sg[512][12] | sw[128]  = 226816 B
#define SMEM_BYTES ((KS_*G_ + KT_*8 + G_*12 + H_) * 4)

__global__ __launch_bounds__(256, 1)
void lstm_k(const float* __restrict__ X,
            const float* __restrict__ bih,
            const float* __restrict__ bhh,
            const float* __restrict__ Wout,
            const float* __restrict__ bout,
            float* __restrict__ out) {
    extern __shared__ float sm[];
    float* sWs = sm;                     // [KS_][512]
    float* sv  = sWs + KS_ * G_;         // [160][8] : rows 0..127 h, 128..159 x_t
    float* sg  = sv + KT_ * 8;           // [512][12] activated gate staging (padded)
    float* sw  = sg + G_ * 12;           // [128] W_out row

    const int tid = threadIdx.x;
    const int n   = blockIdx.x >> 2;
    const int b0  = (blockIdx.x & 3) * 8;
    const int r0  = tid * 2;             // this thread's first gate row
    const bool is_g = ((tid >> 6) == 2); // rows 256..383 are the g gate (tanh)

    // ---- cooperative load of smem weight slice (k in [0,96)) ----
    {
        const float4* src = (const float4*)(g_Wt + (size_t)n * KT_ * G_);
        float4* dst = (float4*)sWs;
        #pragma unroll
        for (int i = 0; i < (KS_ * G_ / 4) / 256; ++i)
            dst[tid + i * 256] = src[tid + i * 256];
    }
    // ---- register-resident weight slice (k in [96,160)) ----
    float wr[2 * KR_];
    {
        const float* ws = g_Wt + ((size_t)n * KT_ + KS_) * G_ + r0;
        #pragma unroll
        for (int kk = 0; kk < KR_; ++kk) {
            float2 w = *(const float2*)(ws + (size_t)kk * G_);
            wr[2 * kk]     = w.x;
            wr[2 * kk + 1] = w.y;
        }
    }
    const float bA = bih[n * G_ + r0]     + bhh[n * G_ + r0];
    const float bB = bih[n * G_ + r0 + 1] + bhh[n * G_ + r0 + 1];
    const float bo = bout[n];
    if (tid < H_) sw[tid] = Wout[n * H_ + tid];

    // ---- init h = 0, load x(0) ----
    for (int i = tid; i < H_ * 8; i += 256) sv[i] = 0.0f;
    {
        int b = tid >> 5, p = tid & 31;
        sv[(H_ + p) * 8 + b] = X[((size_t)(b0 + b) * T_ + 0) * NS_ + p];
    }
    float cq[4] = {0.f, 0.f, 0.f, 0.f};
    const int j  = tid >> 1;             // owned h index in update phase
    const int bq = (tid & 1) * 4;        // owned batch quartet
    __syncthreads();

    for (int t = 0; t < T_; ++t) {
        // ---- Phase A: gates[r0..r0+1][8] over K=160 ----
        unsigned long long a00 = pk2(bA), a01 = a00, a02 = a00, a03 = a00;
        unsigned long long a10 = pk2(bB), a11 = a10, a12 = a10, a13 = a10;
        #pragma unroll 4
        for (int k = 0; k < KS_; ++k) {
            float2 w = *(const float2*)(sWs + k * G_ + r0);
            const unsigned long long* vp = (const unsigned long long*)(sv + k * 8);
            unsigned long long w0 = pk2(w.x), w1 = pk2(w.y);
            unsigned long long v0 = vp[0], v1 = vp[1], v2 = vp[2], v3 = vp[3];
            a00 = ff2(w0, v0, a00); a01 = ff2(w0, v1, a01);
            a02 = ff2(w0, v2, a02); a03 = ff2(w0, v3, a03);
            a10 = ff2(w1, v0, a10); a11 = ff2(w1, v1, a11);
            a12 = ff2(w1, v2, a12); a13 = ff2(w1, v3, a13);
        }
        #pragma unroll
        for (int kk = 0; kk < KR_; ++kk) {
            const unsigned long long* vp = (const unsigned long long*)(sv + (KS_ + kk) * 8);
            unsigned long long w0 = pk2(wr[2 * kk]), w1 = pk2(wr[2 * kk + 1]);
            unsigned long long v0 = vp[0], v1 = vp[1], v2 = vp[2], v3 = vp[3];
            a00 = ff2(w0, v0, a00); a01 = ff2(w0, v1, a01);
            a02 = ff2(w0, v2, a02); a03 = ff2(w0, v3, a03);
            a10 = ff2(w1, v0, a10); a11 = ff2(w1, v1, a11);
            a12 = ff2(w1, v2, a12); a13 = ff2(w1, v3, a13);
        }
        // ---- Phase B: activate + stage ----
        {
            float g0[8], g1[8];
            upk2(a00, g0[0], g0[1]); upk2(a01, g0[2], g0[3]);
            upk2(a02, g0[4], g0[5]); upk2(a03, g0[6], g0[7]);
            upk2(a10, g1[0], g1[1]); upk2(a11, g1[2], g1[3]);
            upk2(a12, g1[4], g1[5]); upk2(a13, g1[6], g1[7]);
            if (is_g) {
                #pragma unroll
                for (int b = 0; b < 8; b++) { g0[b] = tanh_(g0[b]); g1[b] = tanh_(g1[b]); }
            } else {
                #pragma unroll
                for (int b = 0; b < 8; b++) { g0[b] = sigm_(g0[b]); g1[b] = sigm_(g1[b]); }
            }
            *(float4*)(sg + (size_t)r0 * 12)           = make_float4(g0[0], g0[1], g0[2], g0[3]);
            *(float4*)(sg + (size_t)r0 * 12 + 4)       = make_float4(g0[4], g0[5], g0[6], g0[7]);
            *(float4*)(sg + (size_t)(r0 + 1) * 12)     = make_float4(g1[0], g1[1], g1[2], g1[3]);
            *(float4*)(sg + (size_t)(r0 + 1) * 12 + 4) = make_float4(g1[4], g1[5], g1[6], g1[7]);
        }
        __syncthreads();
        // ---- Phase C: c/h update (thread owns (j, bq..bq+3)) ----
        {
            float4 gi = *(const float4*)(sg + (size_t)j * 12 + bq);
            float4 gf = *(const float4*)(sg + (size_t)(H_ + j) * 12 + bq);
            float4 gg = *(const float4*)(sg + (size_t)(2 * H_ + j) * 12 + bq);
            float4 go = *(const float4*)(sg + (size_t)(3 * H_ + j) * 12 + bq);
            float iv[4] = {gi.x, gi.y, gi.z, gi.w};
            float fv[4] = {gf.x, gf.y, gf.z, gf.w};
            float gv[4] = {gg.x, gg.y, gg.z, gg.w};
            float ov[4] = {go.x, go.y, go.z, go.w};
            float hq[4];
            #pragma unroll
            for (int q = 0; q < 4; q++) {
                cq[q] = fv[q] * cq[q] + iv[q] * gv[q];
                hq[q] = ov[q] * tanh_(cq[q]);
            }
            *(float4*)(sv + (size_t)j * 8 + bq) = make_float4(hq[0], hq[1], hq[2], hq[3]);
        }
        // next x_t
        if (t + 1 < T_) {
            int b = tid >> 5, p = tid & 31;
            sv[(H_ + p) * 8 + b] = X[((size_t)(b0 + b) * T_ + (t + 1)) * NS_ + p];
        }
        __syncthreads();
        // ---- Phase D: 1x1 head; warp w -> batch b0+w ----
        {
            int w = tid >> 5, l = tid & 31;
            float s = 0.0f;
            #pragma unroll
            for (int q = 0; q < 4; q++) {
                int jj = l + 32 * q;
                s = fmaf(sv[jj * 8 + w], sw[jj], s);
            }
            #pragma unroll
            for (int m = 16; m > 0; m >>= 1)
                s += __shfl_xor_sync(0xffffffffu, s, m);
            if (l == 0)
                out[((size_t)(b0 + w) * T_ + t) * NS_ + n] = s + bo;
        }
    }

    // ---- final hT, cT: [N,B,H] each, after pred block ----
    {
        const size_t OB  = (size_t)B_ * T_ * NS_;
        const size_t OC  = OB + (size_t)NS_ * B_ * H_;
        #pragma unroll
        for (int q = 0; q < 4; q++) {
            int b = b0 + bq + q;
            out[OB + ((size_t)n * B_ + b) * H_ + j] = sv[(size_t)j * 8 + bq + q];
            out[OC + ((size_t)n * B_ + b) * H_ + j] = cq[q];
        }
    }
}

extern "C" void kernel_launch(void* const* d_in, const int* in_sizes, int n_in,
                              void* d_out, int out_size) {
    const float* X    = (const float*)d_in[0];
    const float* Wih  = (const float*)d_in[1];
    const float* Whh  = (const float*)d_in[2];
    const float* bih  = (const float*)d_in[3];
    const float* bhh  = (const float*)d_in[4];
    const float* Wout = (const float*)d_in[5];
    const float* bout = (const float*)d_in[6];
    float* out = (float*)d_out;

    prep_k<<<dim3(KT_, NS_), G_>>>(Whh, Wih);

    cudaFuncSetAttribute(lstm_k, cudaFuncAttributeMaxDynamicSharedMemorySize, SMEM_BYTES);
    lstm_k<<<NS_ * 4, 256, SMEM_BYTES>>>(X, bih, bhh, Wout, bout, out);
}

// round 8
// speedup vs baseline: 1.0526x; 1.0526x over previous
#include <cuda_runtime.h>

#define B_   32
#define T_   512
#define NS_  32
#define H_   128
#define G_   512      // 4*H
#define KT_  160      // H + NS (h part then x part)
#define KS_  96       // smem-resident k rows
#define KR_  64       // register-resident k rows

// Transposed combined weights: Wt[n][k][r]; k<128 -> W_hh[n][r][k], else W_ih[n][r][k-128]
__device__ float g_Wt[(size_t)NS_ * KT_ * G_];

static __device__ __forceinline__ unsigned long long pk2(float x) {
    unsigned long long r;
    asm("mov.b64 %0, {%1, %1};" : "=l"(r) : "f"(x));
    return r;
}
static __device__ __forceinline__ void upk2(unsigned long long v, float& a, float& b) {
    asm("mov.b64 {%0, %1}, %2;" : "=f"(a), "=f"(b) : "l"(v));
}
static __device__ __forceinline__ unsigned long long ff2(unsigned long long a,
                                                         unsigned long long b,
                                                         unsigned long long c) {
    unsigned long long d;
    asm("fma.rn.f32x2 %0, %1, %2, %3;" : "=l"(d) : "l"(a), "l"(b), "l"(c));
    return d;
}
static __device__ __forceinline__ float sigm_(float x) {
    float e = __expf(-x);
    float r;
    asm("rcp.approx.f32 %0, %1;" : "=f"(r) : "f"(1.0f + e));
    return r;
}
static __device__ __forceinline__ float tanh_(float x) {
    return fmaf(2.0f, sigm_(2.0f * x), -1.0f);
}

// ---------------- prep: transpose weights into g_Wt (coalesced writes) ----
__global__ void prep_k(const float* __restrict__ Whh, const float* __restrict__ Wih) {
    const int k = blockIdx.x;        // 0..159
    const int n = blockIdx.y;        // 0..31
    const int r = threadIdx.x;       // 0..511
    float v;
    if (k < H_) v = Whh[((size_t)n * G_ + r) * H_ + k];
    else        v = Wih[((size_t)n * G_ + r) * NS_ + (k - H_)];
    g_Wt[((size_t)n * KT_ + k) * G_ + r] = v;
}

// ---------------- persistent LSTM kernel ----------------
// smem floats: sWs[96][512] | sv[160][8] | sg[512][12] | sred[64]  = 226560 B
#define SMEM_BYTES ((KS_*G_ + KT_*8 + G_*12 + 64) * 4)

__global__ __launch_bounds__(256, 1)
void lstm_k(const float* __restrict__ X,
            const float* __restrict__ bih,
            const float* __restrict__ bhh,
            const float* __restrict__ Wout,
            const float* __restrict__ bout,
            float* __restrict__ out) {
    extern __shared__ float sm[];
    float* sWs  = sm;                     // [KS_][512]
    float* sv   = sWs + KS_ * G_;         // [160][8] : rows 0..127 h, 128..159 x_t
    float* sg   = sv + KT_ * 8;           // [512][12] activated gate staging (padded)
    float* sred = sg + G_ * 12;           // [8 warps][8 batch] head partials

    const int tid = threadIdx.x;
    const int n   = blockIdx.x >> 2;
    const int b0  = (blockIdx.x & 3) * 8;
    const int r0  = tid * 2;             // this thread's first gate row
    const bool is_g = ((tid >> 6) == 2); // rows 256..383 are the g gate (tanh)

    // ---- cooperative load of smem weight slice (k in [0,96)) ----
    {
        const float4* src = (const float4*)(g_Wt + (size_t)n * KT_ * G_);
        float4* dst = (float4*)sWs;
        #pragma unroll
        for (int i = 0; i < (KS_ * G_ / 4) / 256; ++i)
            dst[tid + i * 256] = src[tid + i * 256];
    }
    // ---- register-resident weight slice (k in [96,160)) ----
    float wr[2 * KR_];
    {
        const float* ws = g_Wt + ((size_t)n * KT_ + KS_) * G_ + r0;
        #pragma unroll
        for (int kk = 0; kk < KR_; ++kk) {
            float2 w = *(const float2*)(ws + (size_t)kk * G_);
            wr[2 * kk]     = w.x;
            wr[2 * kk + 1] = w.y;
        }
    }
    const float bA = bih[n * G_ + r0]     + bhh[n * G_ + r0];
    const float bB = bih[n * G_ + r0 + 1] + bhh[n * G_ + r0 + 1];
    const float bo = bout[n];

    const int j  = tid >> 1;             // owned h index in update phase
    const int bq = (tid & 1) * 4;        // owned batch quartet
    const float swj = Wout[n * H_ + j];  // head weight for owned h index

    // ---- init h = 0, load x(0) ----
    for (int i = tid; i < H_ * 8; i += 256) sv[i] = 0.0f;
    {
        int b = tid >> 5, p = tid & 31;
        sv[(H_ + p) * 8 + b] = X[((size_t)(b0 + b) * T_ + 0) * NS_ + p];
    }
    float cq[4] = {0.f, 0.f, 0.f, 0.f};
    __syncthreads();

    for (int t = 0; t < T_; ++t) {
        // ---- Phase A: gates[r0..r0+1][8] over K=160 ----
        unsigned long long a00 = pk2(bA), a01 = a00, a02 = a00, a03 = a00;
        unsigned long long a10 = pk2(bB), a11 = a10, a12 = a10, a13 = a10;
        #pragma unroll 4
        for (int k = 0; k < KS_; ++k) {
            float2 w = *(const float2*)(sWs + k * G_ + r0);
            ulonglong2 vA = *(const ulonglong2*)(sv + k * 8);
            ulonglong2 vB = *(const ulonglong2*)(sv + k * 8 + 4);
            unsigned long long w0 = pk2(w.x), w1 = pk2(w.y);
            a00 = ff2(w0, vA.x, a00); a01 = ff2(w0, vA.y, a01);
            a02 = ff2(w0, vB.x, a02); a03 = ff2(w0, vB.y, a03);
            a10 = ff2(w1, vA.x, a10); a11 = ff2(w1, vA.y, a11);
            a12 = ff2(w1, vB.x, a12); a13 = ff2(w1, vB.y, a13);
        }
        #pragma unroll
        for (int kk = 0; kk < KR_; ++kk) {
            ulonglong2 vA = *(const ulonglong2*)(sv + (KS_ + kk) * 8);
            ulonglong2 vB = *(const ulonglong2*)(sv + (KS_ + kk) * 8 + 4);
            unsigned long long w0 = pk2(wr[2 * kk]), w1 = pk2(wr[2 * kk + 1]);
            a00 = ff2(w0, vA.x, a00); a01 = ff2(w0, vA.y, a01);
            a02 = ff2(w0, vB.x, a02); a03 = ff2(w0, vB.y, a03);
            a10 = ff2(w1, vA.x, a10); a11 = ff2(w1, vA.y, a11);
            a12 = ff2(w1, vB.x, a12); a13 = ff2(w1, vB.y, a13);
        }
        // ---- Phase B: activate + stage ----
        {
            float g0[8], g1[8];
            upk2(a00, g0[0], g0[1]); upk2(a01, g0[2], g0[3]);
            upk2(a02, g0[4], g0[5]); upk2(a03, g0[6], g0[7]);
            upk2(a10, g1[0], g1[1]); upk2(a11, g1[2], g1[3]);
            upk2(a12, g1[4], g1[5]); upk2(a13, g1[6], g1[7]);
            if (is_g) {
                #pragma unroll
                for (int b = 0; b < 8; b++) { g0[b] = tanh_(g0[b]); g1[b] = tanh_(g1[b]); }
            } else {
                #pragma unroll
                for (int b = 0; b < 8; b++) { g0[b] = sigm_(g0[b]); g1[b] = sigm_(g1[b]); }
            }
            *(float4*)(sg + (size_t)r0 * 12)           = make_float4(g0[0], g0[1], g0[2], g0[3]);
            *(float4*)(sg + (size_t)r0 * 12 + 4)       = make_float4(g0[4], g0[5], g0[6], g0[7]);
            *(float4*)(sg + (size_t)(r0 + 1) * 12)     = make_float4(g1[0], g1[1], g1[2], g1[3]);
            *(float4*)(sg + (size_t)(r0 + 1) * 12 + 4) = make_float4(g1[4], g1[5], g1[6], g1[7]);
        }
        __syncthreads();
        // ---- Phase C: c/h update (thread owns (j, bq..bq+3)) + head partials ----
        {
            float4 gi = *(const float4*)(sg + (size_t)j * 12 + bq);
            float4 gf = *(const float4*)(sg + (size_t)(H_ + j) * 12 + bq);
            float4 gg = *(const float4*)(sg + (size_t)(2 * H_ + j) * 12 + bq);
            float4 go = *(const float4*)(sg + (size_t)(3 * H_ + j) * 12 + bq);
            float iv[4] = {gi.x, gi.y, gi.z, gi.w};
            float fv[4] = {gf.x, gf.y, gf.z, gf.w};
            float gv[4] = {gg.x, gg.y, gg.z, gg.w};
            float ov[4] = {go.x, go.y, go.z, go.w};
            float hq[4], pp[4];
            #pragma unroll
            for (int q = 0; q < 4; q++) {
                cq[q] = fv[q] * cq[q] + iv[q] * gv[q];
                hq[q] = ov[q] * tanh_(cq[q]);
                pp[q] = hq[q] * swj;
            }
            *(float4*)(sv + (size_t)j * 8 + bq) = make_float4(hq[0], hq[1], hq[2], hq[3]);
            // warp reduce over same-parity lanes (16 distinct j per parity group)
            #pragma unroll
            for (int m = 2; m <= 16; m <<= 1) {
                pp[0] += __shfl_xor_sync(0xffffffffu, pp[0], m);
                pp[1] += __shfl_xor_sync(0xffffffffu, pp[1], m);
                pp[2] += __shfl_xor_sync(0xffffffffu, pp[2], m);
                pp[3] += __shfl_xor_sync(0xffffffffu, pp[3], m);
            }
            if ((tid & 31) < 2) {
                int w = tid >> 5;   // lane 0 -> batches 0..3 (bq=0), lane 1 -> 4..7 (bq=4)
                *(float4*)(sred + w * 8 + bq) = make_float4(pp[0], pp[1], pp[2], pp[3]);
            }
        }
        // next x_t
        if (t + 1 < T_) {
            int b = tid >> 5, p = tid & 31;
            sv[(H_ + p) * 8 + b] = X[((size_t)(b0 + b) * T_ + (t + 1)) * NS_ + p];
        }
        __syncthreads();
        // ---- head finish: 8 threads sum the per-warp partials ----
        if (tid < 8) {
            float s = bo;
            #pragma unroll
            for (int w = 0; w < 8; w++) s += sred[w * 8 + tid];
            out[((size_t)(b0 + tid) * T_ + t) * NS_ + n] = s;
        }
    }

    // ---- final hT, cT: [N,B,H] each, after pred block ----
    {
        const size_t OB  = (size_t)B_ * T_ * NS_;
        const size_t OC  = OB + (size_t)NS_ * B_ * H_;
        #pragma unroll
        for (int q = 0; q < 4; q++) {
            int b = b0 + bq + q;
            out[OB + ((size_t)n * B_ + b) * H_ + j] = sv[(size_t)j * 8 + bq + q];
            out[OC + ((size_t)n * B_ + b) * H_ + j] = cq[q];
        }
    }
}

extern "C" void kernel_launch(void* const* d_in, const int* in_sizes, int n_in,
                              void* d_out, int out_size) {
    const float* X    = (const float*)d_in[0];
    const float* Wih  = (const float*)d_in[1];
    const float* Whh  = (const float*)d_in[2];
    const float* bih  = (const float*)d_in[3];
    const float* bhh  = (const float*)d_in[4];
    const float* Wout = (const float*)d_in[5];
    const float* bout = (const float*)d_in[6];
    float* out = (float*)d_out;

    prep_k<<<dim3(KT_, NS_), G_>>>(Whh, Wih);

    cudaFuncSetAttribute(lstm_k, cudaFuncAttributeMaxDynamicSharedMemorySize, SMEM_BYTES);
    lstm_k<<<NS_ * 4, 256, SMEM_BYTES>>>(X, bih, bhh, Wout, bout, out);
}